// round 4
// baseline (speedup 1.0000x reference)
#include <cuda_runtime.h>
#include <math.h>
#include <stddef.h>
#include <stdint.h>

// Problem dims
#define TT 1024
#define BB 256
#define XDIM 64
#define HDIM 256
#define FDIM 256
#define MM (TT*BB)          // 262144 rows for all big GEMMs

// ---------------------------------------------------------------------------
// Scratch (no cudaMalloc allowed)
// ---------------------------------------------------------------------------
__device__ float g_bufA[(size_t)MM * FDIM];   // 256 MB
__device__ float g_bufB[(size_t)MM * FDIM];   // 256 MB

// ---------------------------------------------------------------------------
// helpers
// ---------------------------------------------------------------------------
__device__ __forceinline__ uint32_t f2tf32(float x) {
    uint32_t u;
    asm("cvt.rna.tf32.f32 %0, %1;" : "=r"(u) : "f"(x));
    return u;
}

#define MMA_TF32(c, a, b)                                                   \
    asm volatile("mma.sync.aligned.m16n8k8.row.col.f32.tf32.tf32.f32 "      \
                 "{%0,%1,%2,%3}, {%4,%5,%6,%7}, {%8,%9}, {%0,%1,%2,%3};"    \
                 : "+f"(c[0]), "+f"(c[1]), "+f"(c[2]), "+f"(c[3])           \
                 : "r"(a.x), "r"(a.y), "r"(a.z), "r"(a.w),                  \
                   "r"(b.x), "r"(b.y))

#define FMA2(d, a, b)                                                       \
    asm("fma.rn.f32x2 %0, %1, %2, %0;" : "+l"(d) : "l"(a), "l"(b))
#define ADD2(d, a)                                                          \
    asm("add.rn.f32x2 %0, %0, %1;" : "+l"(d) : "l"(a))
#define UNPACK2(lo, hi, d)                                                  \
    asm("mov.b64 {%0, %1}, %2;" : "=f"(lo), "=f"(hi) : "l"(d))

// ---------------------------------------------------------------------------
// tf32 tensor-core GEMM, 2-stage double-buffered.
// C[M,N] = act( A[M,K] @ B[N,K]^T + bias (+bias2) )
// BM=128, BK=32, 256 threads (8 warps). Warp tile = (WM_AT*16) x (WN_AT*8).
// Fragment-shuffled smem layout (same as R3): conflict-free LDS.128/LDS.64.
// ---------------------------------------------------------------------------
template<int WARPS_M, int WARPS_N, int WM_AT, int WN_AT, int BN>
__global__ __launch_bounds__(256) void gemm_tf32_kernel(
    const float* __restrict__ A, const float* __restrict__ B,
    const float* __restrict__ bias, const float* __restrict__ bias2,
    float* __restrict__ C, int M, int N, int K, int act)
{
    constexpr int BM = 128;
    constexpr int NATB = BN / 8;
    constexpr int BIT_A = (BM * 8) / 256;   // 4 float4/thread per tile
    constexpr int BIT_B = (BN * 8) / 256;
    constexpr int AS_STRIDE = 4 * 8 * 32 * 4;     // u32 per stage (4096)
    constexpr int BS_STRIDE = 4 * NATB * 32 * 2;  // u32 per stage

    extern __shared__ uint32_t smemU[];
    uint32_t* As = smemU;                    // 2 stages
    uint32_t* Bs = smemU + 2 * AS_STRIDE;    // 2 stages

    const int tid  = threadIdx.x;
    const int warp = tid >> 5;
    const int lane = tid & 31;
    const int wm   = warp / WARPS_N;
    const int wn   = warp % WARPS_N;
    const int m0   = blockIdx.y * BM;
    const int n0   = blockIdx.x * BN;

    const int lrow = tid >> 3;
    const int lcol = (tid & 7) * 4;

    float c[WM_AT][WN_AT][4];
#pragma unroll
    for (int mi = 0; mi < WM_AT; mi++)
#pragma unroll
        for (int ni = 0; ni < WN_AT; ni++)
#pragma unroll
            for (int e = 0; e < 4; e++) c[mi][ni][e] = 0.0f;

    float4 aL[BIT_A];
    float4 bL[BIT_B];

    auto LOAD = [&](int kt) {
#pragma unroll
        for (int it = 0; it < BIT_A; it++) {
            int row = lrow + it * 32;
            aL[it] = *(const float4*)(A + (size_t)(m0 + row) * K + kt + lcol);
        }
#pragma unroll
        for (int it = 0; it < BIT_B; it++) {
            int row = lrow + it * 32;
            bL[it] = *(const float4*)(B + (size_t)(n0 + row) * K + kt + lcol);
        }
    };

    auto STORE = [&](int st) {
        uint32_t* Asl = As + st * AS_STRIDE;
        uint32_t* Bsl = Bs + st * BS_STRIDE;
        const int s  = lcol >> 3;
        const int e1 = (lcol >> 2) & 1;
#pragma unroll
        for (int it = 0; it < BIT_A; it++) {
            int row = lrow + it * 32;
            int a = row >> 4, g = row & 7, e0 = (row >> 3) & 1;
            int base = (s * 8 + a) * 32 + g * 4;
            float v[4]; *(float4*)v = aL[it];
#pragma unroll
            for (int j = 0; j < 4; j++)
                Asl[(base + j) * 4 + e0 + 2 * e1] = f2tf32(v[j]);
        }
#pragma unroll
        for (int it = 0; it < BIT_B; it++) {
            int row = lrow + it * 32;
            int atom = row >> 3, g = row & 7;
            int base = (s * NATB + atom) * 32 + g * 4;
            float v[4]; *(float4*)v = bL[it];
#pragma unroll
            for (int j = 0; j < 4; j++)
                Bsl[(base + j) * 2 + e1] = f2tf32(v[j]);
        }
    };

    auto COMP = [&](int st) {
        const uint4* As4 = (const uint4*)(As + st * AS_STRIDE);
        const uint2* Bs2 = (const uint2*)(Bs + st * BS_STRIDE);
#pragma unroll
        for (int s = 0; s < 4; s++) {
            uint4 af[WM_AT];
            uint2 bf[WN_AT];
#pragma unroll
            for (int mi = 0; mi < WM_AT; mi++)
                af[mi] = As4[(s * 8 + wm * WM_AT + mi) * 32 + lane];
#pragma unroll
            for (int ni = 0; ni < WN_AT; ni++)
                bf[ni] = Bs2[(s * NATB + wn * WN_AT + ni) * 32 + lane];
#pragma unroll
            for (int mi = 0; mi < WM_AT; mi++)
#pragma unroll
                for (int ni = 0; ni < WN_AT; ni++)
                    MMA_TF32(c[mi][ni], af[mi], bf[ni]);
        }
    };

    const int ktiles = K >> 5;
    LOAD(0);
    STORE(0);
    __syncthreads();
    for (int kt = 0; kt < ktiles; kt++) {
        if (kt + 1 < ktiles) LOAD((kt + 1) << 5);   // prefetch overlaps COMP
        COMP(kt & 1);
        if (kt + 1 < ktiles) {
            __syncthreads();                        // stage (kt+1)&1 free
            STORE((kt + 1) & 1);
            __syncthreads();
        }
    }

    // epilogue: bias (+bias2), optional tanh
    const int g = lane >> 2, tig = lane & 3;
#pragma unroll
    for (int mi = 0; mi < WM_AT; mi++) {
        int r0 = m0 + (wm * WM_AT + mi) * 16 + g;
#pragma unroll
        for (int ni = 0; ni < WN_AT; ni++) {
            int cc = n0 + (wn * WN_AT + ni) * 8 + 2 * tig;
            float b0v = bias[cc], b1v = bias[cc + 1];
            if (bias2) { b0v += bias2[cc]; b1v += bias2[cc + 1]; }
            float v0 = c[mi][ni][0] + b0v;
            float v1 = c[mi][ni][1] + b1v;
            float v2 = c[mi][ni][2] + b0v;
            float v3 = c[mi][ni][3] + b1v;
            if (act) {
                v0 = tanhf(v0); v1 = tanhf(v1);
                v2 = tanhf(v2); v3 = tanhf(v3);
            }
            *(float2*)(C + (size_t)r0 * N + cc)       = make_float2(v0, v1);
            *(float2*)(C + (size_t)(r0 + 8) * N + cc) = make_float2(v2, v3);
        }
    }
}

// ---------------------------------------------------------------------------
// Recurrence v3. 128 blocks x 256 threads; block owns 2 batch rows.
// Thread i computes output unit i for both batches: NO cross-thread reduction.
// Whh row i: cols [0,128) in 64 ull REGISTERS; cols [128,256) in swizzled smem.
// h stored batch-interleaved at pair granularity: hs[q] = 16B
// {h0[2q],h0[2q+1],h1[2q],h1[2q+1]} -> one ulonglong2 broadcast load feeds
// both batches' FMA2 with zero pack instructions. Ping-pong h => 1 bar/step.
// ---------------------------------------------------------------------------
#define R3_SMEM_BYTES (256*32*16 + 2*128*16)   // 128KB W + 4KB h = 135168 B

__global__ __launch_bounds__(256, 1) void recurrence3_kernel(
    const float* __restrict__ Z, const float* __restrict__ Whh,
    float* __restrict__ Hall)
{
    extern __shared__ unsigned char rsm[];
    float4*     Wsm4 = (float4*)rsm;                     // [256 rows][32 chunks]
    ulonglong2* Wsm2 = (ulonglong2*)rsm;
    ulonglong2* hs2  = (ulonglong2*)(rsm + 256 * 32 * 16);  // [2][128]

    const int tid = threadIdx.x;
    const int b0 = blockIdx.x * 2;
    const int swl = tid & 31;

    // W upper half (cols 128..255) into swizzled smem chunks
    for (int idx = tid; idx < 256 * 32; idx += 256) {
        int row = idx >> 5, q2 = idx & 31;
        Wsm4[row * 32 + (q2 ^ (row & 31))] =
            *(const float4*)(Whh + row * 256 + 128 + q2 * 4);
    }
    // zero both h ping-pong buffers (2*128 = 256 ulonglong2 entries)
    {
        ulonglong2 zz; zz.x = 0ULL; zz.y = 0ULL;
        hs2[tid] = zz;
    }
    // W lower half (cols 0..127) into registers as 64 pairs
    unsigned long long wr[64];
#pragma unroll
    for (int q = 0; q < 64; q++)
        wr[q] = *(const unsigned long long*)(Whh + (size_t)tid * 256 + 2 * q);

    const float a_i = (tid < 86) ? 0.001f : (tid < 171) ? 0.01f : 0.1f;
    float h0t = 0.0f, h1t = 0.0f;
    float z0 = Z[(size_t)b0 * HDIM + tid];
    float z1 = Z[(size_t)b0 * HDIM + 256 + tid];
    __syncthreads();

    int cur = 0;
    for (int t = 0; t < TT; t++) {
        // prefetch next Z (hidden under this step's FMA loop)
        float zn0 = 0.0f, zn1 = 0.0f;
        if (t + 1 < TT) {
            const float* Zn = Z + ((size_t)(t + 1) * BB + b0) * HDIM;
            zn0 = Zn[tid];
            zn1 = Zn[256 + tid];
        }
        // record pre-update h (y_t is generated from h_t)
        float* Ht = Hall + ((size_t)t * BB + b0) * HDIM;
        Ht[tid] = h0t;
        Ht[256 + tid] = h1t;

        const ulonglong2* hc = hs2 + cur * 128;
        unsigned long long a0[4] = {0, 0, 0, 0};
        unsigned long long a1[4] = {0, 0, 0, 0};

        // register-resident W (j = 0..127)
#pragma unroll
        for (int q = 0; q < 64; q++) {
            ulonglong2 hv = hc[q];            // broadcast LDS.128
            FMA2(a0[q & 3], wr[q], hv.x);
            FMA2(a1[q & 3], wr[q], hv.y);
        }
        // smem-resident W (j = 128..255)
#pragma unroll
        for (int q2 = 0; q2 < 32; q2++) {
            ulonglong2 wv  = Wsm2[tid * 32 + (q2 ^ swl)];
            ulonglong2 hva = hc[64 + 2 * q2];
            ulonglong2 hvb = hc[64 + 2 * q2 + 1];
            FMA2(a0[(2 * q2) & 3],     wv.x, hva.x);
            FMA2(a1[(2 * q2) & 3],     wv.x, hva.y);
            FMA2(a0[(2 * q2 + 1) & 3], wv.y, hvb.x);
            FMA2(a1[(2 * q2 + 1) & 3], wv.y, hvb.y);
        }

        // horizontal reduce 4 packed accumulators -> scalar
        ADD2(a0[0], a0[1]); ADD2(a0[2], a0[3]); ADD2(a0[0], a0[2]);
        ADD2(a1[0], a1[1]); ADD2(a1[2], a1[3]); ADD2(a1[0], a1[2]);
        float s0lo, s0hi, s1lo, s1hi;
        UNPACK2(s0lo, s0hi, a0[0]);
        UNPACK2(s1lo, s1hi, a1[0]);

        float hr0 = tanhf(s0lo + s0hi + z0);
        float hr1 = tanhf(s1lo + s1hi + z1);
        h0t = fmaf(a_i, hr0 - h0t, h0t);
        h1t = fmaf(a_i, hr1 - h1t, h1t);

        // publish into ping-pong pair-interleaved layout
        int nxt = cur ^ 1;
        float* hw = (float*)(hs2 + nxt * 128);
        hw[(tid >> 1) * 4 + (tid & 1)]     = h0t;
        hw[(tid >> 1) * 4 + (tid & 1) + 2] = h1t;
        __syncthreads();
        cur = nxt;
        z0 = zn0; z1 = zn1;
    }
}

// ---------------------------------------------------------------------------
// Launch. Input order: x,Wx0,bx0,Wx1,bx1,Wih,Whh,bih,bhh,Wh0,bh0,Wh1,bh1,Wg,bg
// ---------------------------------------------------------------------------
extern "C" void kernel_launch(void* const* d_in, const int* in_sizes, int n_in,
                              void* d_out, int out_size)
{
    const float* x   = (const float*)d_in[0];
    const float* Wx0 = (const float*)d_in[1];
    const float* bx0 = (const float*)d_in[2];
    const float* Wx1 = (const float*)d_in[3];
    const float* bx1 = (const float*)d_in[4];
    const float* Wih = (const float*)d_in[5];
    const float* Whh = (const float*)d_in[6];
    const float* bih = (const float*)d_in[7];
    const float* bhh = (const float*)d_in[8];
    const float* Wh0 = (const float*)d_in[9];
    const float* bh0 = (const float*)d_in[10];
    const float* Wh1 = (const float*)d_in[11];
    const float* bh1 = (const float*)d_in[12];
    const float* Wg  = (const float*)d_in[13];
    const float* bg  = (const float*)d_in[14];
    float* y = (float*)d_out;

    float *bufA, *bufB;
    cudaGetSymbolAddress((void**)&bufA, g_bufA);
    cudaGetSymbolAddress((void**)&bufB, g_bufB);

    // dynamic smem sizes
    const int smem128 = (2 * 4096 + 2 * 4096) * 4;   // 64 KB  (BN=128)
    const int smem64  = (2 * 4096 + 2 * 2048) * 4;   // 48 KB  (BN=64)
    cudaFuncSetAttribute(gemm_tf32_kernel<2,4,4,4,128>,
                         cudaFuncAttributeMaxDynamicSharedMemorySize, smem128);
    cudaFuncSetAttribute(gemm_tf32_kernel<4,2,2,4,64>,
                         cudaFuncAttributeMaxDynamicSharedMemorySize, smem64);
    cudaFuncSetAttribute(recurrence3_kernel,
                         cudaFuncAttributeMaxDynamicSharedMemorySize, R3_SMEM_BYTES);

    dim3 blk(256);
    dim3 gN256(FDIM / 128, MM / 128);   // (2, 2048) N-tiles fastest -> L2 A reuse
    dim3 gN64 (1,          MM / 128);

    // feat1 = tanh(x @ Wx0^T + bx0)
    gemm_tf32_kernel<2,4,4,4,128><<<gN256, blk, smem128>>>(x, Wx0, bx0, nullptr,
                                                           bufA, MM, FDIM, XDIM, 1);
    // feat2 = tanh(feat1 @ Wx1^T + bx1)
    gemm_tf32_kernel<2,4,4,4,128><<<gN256, blk, smem128>>>(bufA, Wx1, bx1, nullptr,
                                                           bufB, MM, FDIM, FDIM, 1);
    // Z = feat2 @ Wih^T + bih + bhh
    gemm_tf32_kernel<2,4,4,4,128><<<gN256, blk, smem128>>>(bufB, Wih, bih, bhh,
                                                           bufA, MM, HDIM, FDIM, 0);
    // sequential scan: Hall[t] = h_t ; h update   (Z in bufA, Hall -> bufB)
    recurrence3_kernel<<<BB / 2, blk, R3_SMEM_BYTES>>>(bufA, Whh, bufB);
    // d1 = tanh(Hall @ Wh0^T + bh0)
    gemm_tf32_kernel<2,4,4,4,128><<<gN256, blk, smem128>>>(bufB, Wh0, bh0, nullptr,
                                                           bufA, MM, FDIM, HDIM, 1);
    // d2 = tanh(d1 @ Wh1^T + bh1)
    gemm_tf32_kernel<2,4,4,4,128><<<gN256, blk, smem128>>>(bufA, Wh1, bh1, nullptr,
                                                           bufB, MM, FDIM, FDIM, 1);
    // y = d2 @ Wg^T + bg
    gemm_tf32_kernel<4,2,2,4,64><<<gN64, blk, smem64>>>(bufB, Wg, bg, nullptr,
                                                        y, MM, XDIM, FDIM, 0);
}

// round 7
// speedup vs baseline: 1.0737x; 1.0737x over previous
#include <cuda_runtime.h>
#include <math.h>
#include <stddef.h>
#include <stdint.h>

// Problem dims
#define TT 1024
#define BB 256
#define XDIM 64
#define HDIM 256
#define FDIM 256
#define MM (TT*BB)          // 262144 rows for all big GEMMs

// ---------------------------------------------------------------------------
// Scratch (no cudaMalloc allowed)
// ---------------------------------------------------------------------------
__device__ float g_bufA[(size_t)MM * FDIM];   // 256 MB
__device__ float g_bufB[(size_t)MM * FDIM];   // 256 MB

// ---------------------------------------------------------------------------
// helpers
// ---------------------------------------------------------------------------
__device__ __forceinline__ uint32_t f2tf32(float x) {
    uint32_t u;
    asm("cvt.rna.tf32.f32 %0, %1;" : "=r"(u) : "f"(x));
    return u;
}

#define MMA_TF32(c, a, b)                                                   \
    asm volatile("mma.sync.aligned.m16n8k8.row.col.f32.tf32.tf32.f32 "      \
                 "{%0,%1,%2,%3}, {%4,%5,%6,%7}, {%8,%9}, {%0,%1,%2,%3};"    \
                 : "+f"(c[0]), "+f"(c[1]), "+f"(c[2]), "+f"(c[3])           \
                 : "r"(a.x), "r"(a.y), "r"(a.z), "r"(a.w),                  \
                   "r"(b.x), "r"(b.y))

#define FMA2(d, a, b)                                                       \
    asm("fma.rn.f32x2 %0, %1, %2, %0;" : "+l"(d) : "l"(a), "l"(b))
#define ADD2(d, a)                                                          \
    asm("add.rn.f32x2 %0, %0, %1;" : "+l"(d) : "l"(a))
#define UNPACK2(lo, hi, d)                                                  \
    asm("mov.b64 {%0, %1}, %2;" : "=f"(lo), "=f"(hi) : "l"(d))

// ---------------------------------------------------------------------------
// tf32 tensor-core GEMM, 2-stage double-buffered, fragment-shuffled smem.
// C[M,N] = act( A[M,K] @ B[N,K]^T + bias (+bias2) )
// BM=128, BK=32. THREADS=512 -> 16 warps, 32x32 warp tiles (low reg pressure,
// 4 warps/SMSP for latency hiding). THREADS=256 variant for BN=64.
// ---------------------------------------------------------------------------
template<int THREADS, int WARPS_M, int WARPS_N, int WM_AT, int WN_AT, int BN>
__global__ __launch_bounds__(THREADS) void gemm_tf32_kernel(
    const float* __restrict__ A, const float* __restrict__ B,
    const float* __restrict__ bias, const float* __restrict__ bias2,
    float* __restrict__ C, int M, int N, int K, int act)
{
    constexpr int BM = 128;
    constexpr int NATB = BN / 8;
    constexpr int BIT_A = (BM * 8) / THREADS;
    constexpr int BIT_B = (BN * 8) / THREADS;
    constexpr int AS_STRIDE = 4 * 8 * 32 * 4;       // 4096 u32 per stage
    constexpr int BS_STRIDE = 4 * NATB * 32 * 2;    // u32 per stage

    extern __shared__ uint32_t smemU[];
    uint32_t* As = smemU;
    uint32_t* Bs = smemU + 2 * AS_STRIDE;

    const int tid  = threadIdx.x;
    const int warp = tid >> 5;
    const int lane = tid & 31;
    const int wm   = warp / WARPS_N;
    const int wn   = warp % WARPS_N;
    const int m0   = blockIdx.y * BM;
    const int n0   = blockIdx.x * BN;

    const int lrow0 = tid >> 3;
    const int lcol  = (tid & 7) * 4;

    float c[WM_AT][WN_AT][4];
#pragma unroll
    for (int mi = 0; mi < WM_AT; mi++)
#pragma unroll
        for (int ni = 0; ni < WN_AT; ni++)
#pragma unroll
            for (int e = 0; e < 4; e++) c[mi][ni][e] = 0.0f;

    float4 aL[BIT_A];
    float4 bL[BIT_B];

    auto LOAD = [&](int kt) {
#pragma unroll
        for (int it = 0; it < BIT_A; it++) {
            int row = lrow0 + it * (THREADS / 8);
            aL[it] = *(const float4*)(A + (size_t)(m0 + row) * K + kt + lcol);
        }
#pragma unroll
        for (int it = 0; it < BIT_B; it++) {
            int row = lrow0 + it * (THREADS / 8);
            bL[it] = *(const float4*)(B + (size_t)(n0 + row) * K + kt + lcol);
        }
    };

    auto STORE = [&](int st) {
        uint32_t* Asl = As + st * AS_STRIDE;
        uint32_t* Bsl = Bs + st * BS_STRIDE;
        const int s  = lcol >> 3;
        const int e1 = (lcol >> 2) & 1;
#pragma unroll
        for (int it = 0; it < BIT_A; it++) {
            int row = lrow0 + it * (THREADS / 8);
            int a = row >> 4, g = row & 7, e0 = (row >> 3) & 1;
            int base = (s * 8 + a) * 32 + g * 4;
            float v[4]; *(float4*)v = aL[it];
#pragma unroll
            for (int j = 0; j < 4; j++)
                Asl[(base + j) * 4 + e0 + 2 * e1] = f2tf32(v[j]);
        }
#pragma unroll
        for (int it = 0; it < BIT_B; it++) {
            int row = lrow0 + it * (THREADS / 8);
            int atom = row >> 3, g = row & 7;
            int base = (s * NATB + atom) * 32 + g * 4;
            float v[4]; *(float4*)v = bL[it];
#pragma unroll
            for (int j = 0; j < 4; j++)
                Bsl[(base + j) * 2 + e1] = f2tf32(v[j]);
        }
    };

    auto COMP = [&](int st) {
        const uint4* As4 = (const uint4*)(As + st * AS_STRIDE);
        const uint2* Bs2 = (const uint2*)(Bs + st * BS_STRIDE);
#pragma unroll
        for (int s = 0; s < 4; s++) {
            uint4 af[WM_AT];
            uint2 bf[WN_AT];
#pragma unroll
            for (int mi = 0; mi < WM_AT; mi++)
                af[mi] = As4[(s * 8 + wm * WM_AT + mi) * 32 + lane];
#pragma unroll
            for (int ni = 0; ni < WN_AT; ni++)
                bf[ni] = Bs2[(s * NATB + wn * WN_AT + ni) * 32 + lane];
#pragma unroll
            for (int mi = 0; mi < WM_AT; mi++)
#pragma unroll
                for (int ni = 0; ni < WN_AT; ni++)
                    MMA_TF32(c[mi][ni], af[mi], bf[ni]);
        }
    };

    const int ktiles = K >> 5;
    LOAD(0);
    STORE(0);
    __syncthreads();
    for (int kt = 0; kt < ktiles; kt++) {
        if (kt + 1 < ktiles) LOAD((kt + 1) << 5);   // prefetch overlaps COMP
        COMP(kt & 1);
        if (kt + 1 < ktiles) {
            __syncthreads();
            STORE((kt + 1) & 1);
            __syncthreads();
        }
    }

    // epilogue
    const int g = lane >> 2, tig = lane & 3;
#pragma unroll
    for (int mi = 0; mi < WM_AT; mi++) {
        int r0 = m0 + (wm * WM_AT + mi) * 16 + g;
#pragma unroll
        for (int ni = 0; ni < WN_AT; ni++) {
            int cc = n0 + (wn * WN_AT + ni) * 8 + 2 * tig;
            float b0v = bias[cc], b1v = bias[cc + 1];
            if (bias2) { b0v += bias2[cc]; b1v += bias2[cc + 1]; }
            float v0 = c[mi][ni][0] + b0v;
            float v1 = c[mi][ni][1] + b1v;
            float v2 = c[mi][ni][2] + b0v;
            float v3 = c[mi][ni][3] + b1v;
            if (act) {
                v0 = tanhf(v0); v1 = tanhf(v1);
                v2 = tanhf(v2); v3 = tanhf(v3);
            }
            *(float2*)(C + (size_t)r0 * N + cc)       = make_float2(v0, v1);
            *(float2*)(C + (size_t)(r0 + 8) * N + cc) = make_float2(v2, v3);
        }
    }
}

// ---------------------------------------------------------------------------
// Recurrence v4. 128 blocks x 256 threads; block owns 2 batch rows.
// Thread i computes output unit i for both batches (no cross-thread reduce).
// W row i: cols [0,64) in 32 ull REGISTERS; cols [64,256) in smem with
// padded stride (49 float4/row -> conflict-free). ~130 regs total so ptxas
// can pipeline the broadcast h loads past their FMA2 consumers.
// h batch-interleaved at pair granularity; ping-pong => 1 barrier/step.
// ---------------------------------------------------------------------------
#define R4_W_F4_STRIDE 49
#define R4_SMEM_BYTES (256 * R4_W_F4_STRIDE * 16 + 2 * 128 * 16)  // 204800 B

__global__ __launch_bounds__(256, 1) void recurrence4_kernel(
    const float* __restrict__ Z, const float* __restrict__ Whh,
    float* __restrict__ Hall)
{
    extern __shared__ unsigned char rsm[];
    float4*     Wsm4 = (float4*)rsm;                 // [256][49] (48 used)
    ulonglong2* Wsm2 = (ulonglong2*)rsm;
    ulonglong2* hs2  = (ulonglong2*)(rsm + 256 * R4_W_F4_STRIDE * 16);

    const int tid = threadIdx.x;
    const int b0 = blockIdx.x * 2;

    // W cols [64,256) -> smem, padded row stride 49 float4
    for (int idx = tid; idx < 256 * 48; idx += 256) {
        int row = idx / 48, c = idx % 48;
        Wsm4[row * R4_W_F4_STRIDE + c] =
            *(const float4*)(Whh + (size_t)row * 256 + 64 + c * 4);
    }
    // zero h ping-pong buffers
    {
        ulonglong2 zz; zz.x = 0ULL; zz.y = 0ULL;
        hs2[tid] = zz;
    }
    // W cols [0,64) -> 32 ull register pairs
    unsigned long long wr[32];
#pragma unroll
    for (int q = 0; q < 32; q++)
        wr[q] = *(const unsigned long long*)(Whh + (size_t)tid * 256 + 2 * q);

    const float a_i = (tid < 86) ? 0.001f : (tid < 171) ? 0.01f : 0.1f;
    float h0t = 0.0f, h1t = 0.0f;
    float z0 = Z[(size_t)b0 * HDIM + tid];
    float z1 = Z[(size_t)b0 * HDIM + 256 + tid];
    __syncthreads();

    int cur = 0;
    for (int t = 0; t < TT; t++) {
        // prefetch next Z (hidden under this step's FMA loop)
        float zn0 = 0.0f, zn1 = 0.0f;
        if (t + 1 < TT) {
            const float* Zn = Z + ((size_t)(t + 1) * BB + b0) * HDIM;
            zn0 = Zn[tid];
            zn1 = Zn[256 + tid];
        }
        // record pre-update h (y_t comes from h_t)
        float* Ht = Hall + ((size_t)t * BB + b0) * HDIM;
        Ht[tid] = h0t;
        Ht[256 + tid] = h1t;

        const ulonglong2* hc = hs2 + cur * 128;
        unsigned long long a0[4] = {0, 0, 0, 0};
        unsigned long long a1[4] = {0, 0, 0, 0};

        // register-resident W (cols 0..63, pairs q = 0..31)
#pragma unroll
        for (int q = 0; q < 32; q++) {
            ulonglong2 hv = hc[q];                // broadcast LDS.128
            FMA2(a0[q & 3], wr[q], hv.x);
            FMA2(a1[q & 3], wr[q], hv.y);
        }
        // smem-resident W (cols 64..255, 48 chunks of 4 cols)
#pragma unroll
        for (int q2 = 0; q2 < 48; q2++) {
            ulonglong2 wv  = Wsm2[tid * R4_W_F4_STRIDE + q2];
            ulonglong2 hva = hc[32 + 2 * q2];
            ulonglong2 hvb = hc[33 + 2 * q2];
            FMA2(a0[(2 * q2) & 3],     wv.x, hva.x);
            FMA2(a1[(2 * q2) & 3],     wv.x, hva.y);
            FMA2(a0[(2 * q2 + 1) & 3], wv.y, hvb.x);
            FMA2(a1[(2 * q2 + 1) & 3], wv.y, hvb.y);
        }

        // horizontal reduce packed accumulators
        ADD2(a0[0], a0[1]); ADD2(a0[2], a0[3]); ADD2(a0[0], a0[2]);
        ADD2(a1[0], a1[1]); ADD2(a1[2], a1[3]); ADD2(a1[0], a1[2]);
        float s0lo, s0hi, s1lo, s1hi;
        UNPACK2(s0lo, s0hi, a0[0]);
        UNPACK2(s1lo, s1hi, a1[0]);

        float hr0 = tanhf(s0lo + s0hi + z0);
        float hr1 = tanhf(s1lo + s1hi + z1);
        h0t = fmaf(a_i, hr0 - h0t, h0t);
        h1t = fmaf(a_i, hr1 - h1t, h1t);

        // publish into ping-pong pair-interleaved layout
        int nxt = cur ^ 1;
        float* hw = (float*)(hs2 + nxt * 128);
        hw[(tid >> 1) * 4 + (tid & 1)]     = h0t;
        hw[(tid >> 1) * 4 + (tid & 1) + 2] = h1t;
        __syncthreads();
        cur = nxt;
        z0 = zn0; z1 = zn1;
    }
}

// ---------------------------------------------------------------------------
// Launch. Input order: x,Wx0,bx0,Wx1,bx1,Wih,Whh,bih,bhh,Wh0,bh0,Wh1,bh1,Wg,bg
// ---------------------------------------------------------------------------
extern "C" void kernel_launch(void* const* d_in, const int* in_sizes, int n_in,
                              void* d_out, int out_size)
{
    const float* x   = (const float*)d_in[0];
    const float* Wx0 = (const float*)d_in[1];
    const float* bx0 = (const float*)d_in[2];
    const float* Wx1 = (const float*)d_in[3];
    const float* bx1 = (const float*)d_in[4];
    const float* Wih = (const float*)d_in[5];
    const float* Whh = (const float*)d_in[6];
    const float* bih = (const float*)d_in[7];
    const float* bhh = (const float*)d_in[8];
    const float* Wh0 = (const float*)d_in[9];
    const float* bh0 = (const float*)d_in[10];
    const float* Wh1 = (const float*)d_in[11];
    const float* bh1 = (const float*)d_in[12];
    const float* Wg  = (const float*)d_in[13];
    const float* bg  = (const float*)d_in[14];
    float* y = (float*)d_out;

    float *bufA, *bufB;
    cudaGetSymbolAddress((void**)&bufA, g_bufA);
    cudaGetSymbolAddress((void**)&bufB, g_bufB);

    // instantiations
    auto G512 = gemm_tf32_kernel<512, 4, 4, 2, 4, 128>;  // BN=128, 16 warps
    auto G256 = gemm_tf32_kernel<256, 4, 2, 2, 4, 64>;   // BN=64,  8 warps

    const int smem512 = (2 * 4096 + 2 * 4096) * 4;   // 64 KB
    const int smem256 = (2 * 4096 + 2 * 2048) * 4;   // 48 KB
    cudaFuncSetAttribute(G512, cudaFuncAttributeMaxDynamicSharedMemorySize, smem512);
    cudaFuncSetAttribute(G256, cudaFuncAttributeMaxDynamicSharedMemorySize, smem256);
    cudaFuncSetAttribute(recurrence4_kernel,
                         cudaFuncAttributeMaxDynamicSharedMemorySize, R4_SMEM_BYTES);

    dim3 gBig(FDIM / 128, MM / 128);   // (2, 2048), N-tiles fastest -> L2 A reuse
    dim3 gOut(1,          MM / 128);

    // feat1 = tanh(x @ Wx0^T + bx0)
    G512<<<gBig, 512, smem512>>>(x, Wx0, bx0, nullptr, bufA, MM, FDIM, XDIM, 1);
    // feat2 = tanh(feat1 @ Wx1^T + bx1)
    G512<<<gBig, 512, smem512>>>(bufA, Wx1, bx1, nullptr, bufB, MM, FDIM, FDIM, 1);
    // Z = feat2 @ Wih^T + bih + bhh
    G512<<<gBig, 512, smem512>>>(bufB, Wih, bih, bhh, bufA, MM, HDIM, FDIM, 0);
    // sequential scan: Hall[t] = h_t ; h update  (Z in bufA, Hall -> bufB)
    recurrence4_kernel<<<BB / 2, 256, R4_SMEM_BYTES>>>(bufA, Whh, bufB);
    // d1 = tanh(Hall @ Wh0^T + bh0)
    G512<<<gBig, 512, smem512>>>(bufB, Wh0, bh0, nullptr, bufA, MM, FDIM, HDIM, 1);
    // d2 = tanh(d1 @ Wh1^T + bh1)
    G512<<<gBig, 512, smem512>>>(bufA, Wh1, bh1, nullptr, bufB, MM, FDIM, FDIM, 1);
    // y = d2 @ Wg^T + bg
    G256<<<gOut, 256, smem256>>>(bufB, Wg, bg, nullptr, y, MM, XDIM, FDIM, 0);
}

// round 8
// speedup vs baseline: 1.4098x; 1.3129x over previous
#include <cuda_runtime.h>
#include <math.h>
#include <stddef.h>
#include <stdint.h>

// Problem dims
#define TT 1024
#define BB 256
#define XDIM 64
#define HDIM 256
#define FDIM 256
#define MM (TT*BB)          // 262144 rows for all big GEMMs

// ---------------------------------------------------------------------------
// Scratch (no cudaMalloc allowed)
// ---------------------------------------------------------------------------
__device__ float g_bufA[(size_t)MM * FDIM];   // 256 MB
__device__ float g_bufB[(size_t)MM * FDIM];   // 256 MB
__device__ float g_wr[294912];                // rounded weights, 1.2 MB

// weight offsets inside g_wr
#define WR_WX0 0
#define WR_WX1 16384
#define WR_WIH 81920
#define WR_WH0 147456
#define WR_WH1 212992
#define WR_WG  278528

// ---------------------------------------------------------------------------
// helpers
// ---------------------------------------------------------------------------
__device__ __forceinline__ uint32_t f2tf32(float x) {
    uint32_t u;
    asm("cvt.rna.tf32.f32 %0, %1;" : "=r"(u) : "f"(x));
    return u;
}
__device__ __forceinline__ float roundtf(float x) {
    return __uint_as_float(f2tf32(x));
}

#define MMA_TF32(c, a0, a1, a2, a3, b0, b1)                                 \
    asm volatile("mma.sync.aligned.m16n8k8.row.col.f32.tf32.tf32.f32 "      \
                 "{%0,%1,%2,%3}, {%4,%5,%6,%7}, {%8,%9}, {%0,%1,%2,%3};"    \
                 : "+f"(c[0]), "+f"(c[1]), "+f"(c[2]), "+f"(c[3])           \
                 : "r"(a0), "r"(a1), "r"(a2), "r"(a3), "r"(b0), "r"(b1))

#define FMA2(d, a, b)                                                       \
    asm("fma.rn.f32x2 %0, %1, %2, %0;" : "+l"(d) : "l"(a), "l"(b))
#define ADD2(d, a)                                                          \
    asm("add.rn.f32x2 %0, %0, %1;" : "+l"(d) : "l"(a))
#define UNPACK2(lo, hi, d)                                                  \
    asm("mov.b64 {%0, %1}, %2;" : "=f"(lo), "=f"(hi) : "l"(d))

__device__ __forceinline__ void cp16(uint32_t dst, const void* src) {
    asm volatile("cp.async.ca.shared.global [%0], [%1], 16;\n"
                 :: "r"(dst), "l"(src));
}
__device__ __forceinline__ void cp_commit() {
    asm volatile("cp.async.commit_group;\n" ::);
}
template<int N>
__device__ __forceinline__ void cp_wait() {
    asm volatile("cp.async.wait_group %0;\n" :: "n"(N));
}

// ---------------------------------------------------------------------------
// Pre-round inputs to tf32 (idempotent; makes GEMM loads conversion-free)
// ---------------------------------------------------------------------------
__global__ void round_tf32_kernel(const float* __restrict__ src,
                                  float* __restrict__ dst, int n)
{
    int idx = (blockIdx.x * blockDim.x + threadIdx.x) * 4;
    if (idx < n) {
        float4 v = *(const float4*)(src + idx);
        v.x = roundtf(v.x); v.y = roundtf(v.y);
        v.z = roundtf(v.z); v.w = roundtf(v.w);
        *(float4*)(dst + idx) = v;
    }
}

// ---------------------------------------------------------------------------
// tf32 tensor-core GEMM with cp.async 3-stage pipeline.
// C[M,N] = act( A[M,K] @ B[N,K]^T + bias (+bias2) ); act => tanh + tf32-round.
// BM=128, BK=32. smem tiles row-major with 16B-chunk XOR swizzle
// (chunk c of row r stored at c ^ (r&7)) -> conflict-free LDS.32 frag loads.
// Inputs MUST be pre-rounded to tf32 (raw bits fed to mma).
// ---------------------------------------------------------------------------
template<int THREADS, int WARPS_M, int WARPS_N, int BN, int STAGES>
__global__ __launch_bounds__(THREADS) void gemm_cp_kernel(
    const float* __restrict__ A, const float* __restrict__ B,
    const float* __restrict__ bias, const float* __restrict__ bias2,
    float* __restrict__ C, int M, int N, int K, int act)
{
    constexpr int BM = 128, BK = 32;
    constexpr int WM_AT = (BM / WARPS_M) / 16;   // m-atoms per warp (2)
    constexpr int WN_AT = (BN / WARPS_N) / 8;    // n-atoms per warp (4)
    constexpr int A_FLOATS = BM * BK;            // 4096
    constexpr int B_FLOATS = BN * BK;
    constexpr int A_CH = (A_FLOATS / 4) / THREADS;   // 16B chunks per thread
    constexpr int B_CH = (B_FLOATS / 4) / THREADS;

    extern __shared__ float smf[];
    float* As = smf;                         // [STAGES][A_FLOATS]
    float* Bs = smf + STAGES * A_FLOATS;     // [STAGES][B_FLOATS]

    const int tid  = threadIdx.x;
    const int warp = tid >> 5;
    const int lane = tid & 31;
    const int wm   = warp / WARPS_N;
    const int wn   = warp % WARPS_N;
    const int m0   = blockIdx.y * BM;
    const int n0   = blockIdx.x * BN;
    const int g    = lane >> 2;
    const int tig  = lane & 3;

    float c[WM_AT][WN_AT][4];
#pragma unroll
    for (int mi = 0; mi < WM_AT; mi++)
#pragma unroll
        for (int ni = 0; ni < WN_AT; ni++)
#pragma unroll
            for (int e = 0; e < 4; e++) c[mi][ni][e] = 0.0f;

    const int ktiles = K >> 5;

    auto ISSUE = [&](int st, int kt, bool valid) {
        if (valid) {
            float* Asl = As + st * A_FLOATS;
            float* Bsl = Bs + st * B_FLOATS;
#pragma unroll
            for (int it = 0; it < A_CH; it++) {
                int ch = tid + it * THREADS;
                int row = ch >> 3, cc = ch & 7;
                const float* src = A + (size_t)(m0 + row) * K + kt + cc * 4;
                uint32_t dst = (uint32_t)__cvta_generic_to_shared(
                    Asl + row * 32 + ((cc ^ (row & 7)) << 2));
                cp16(dst, src);
            }
#pragma unroll
            for (int it = 0; it < B_CH; it++) {
                int ch = tid + it * THREADS;
                int row = ch >> 3, cc = ch & 7;
                const float* src = B + (size_t)(n0 + row) * K + kt + cc * 4;
                uint32_t dst = (uint32_t)__cvta_generic_to_shared(
                    Bsl + row * 32 + ((cc ^ (row & 7)) << 2));
                cp16(dst, src);
            }
        }
        cp_commit();
    };

    auto COMP = [&](int st) {
        const float* Asl = As + st * A_FLOATS;
        const float* Bsl = Bs + st * B_FLOATS;
#pragma unroll
        for (int s = 0; s < 4; s++) {
            const int x0 = ((2 * s) ^ g) * 4 + tig;       // k = s*8+tig
            const int x1 = ((2 * s + 1) ^ g) * 4 + tig;   // k = s*8+tig+4
            uint32_t af[WM_AT][4];
            uint32_t bf[WN_AT][2];
#pragma unroll
            for (int mi = 0; mi < WM_AT; mi++) {
                int rb = (wm * WM_AT + mi) * 16 + g;
                af[mi][0] = __float_as_uint(Asl[rb * 32 + x0]);
                af[mi][1] = __float_as_uint(Asl[(rb + 8) * 32 + x0]);
                af[mi][2] = __float_as_uint(Asl[rb * 32 + x1]);
                af[mi][3] = __float_as_uint(Asl[(rb + 8) * 32 + x1]);
            }
#pragma unroll
            for (int ni = 0; ni < WN_AT; ni++) {
                int nb = (wn * WN_AT + ni) * 8 + g;
                bf[ni][0] = __float_as_uint(Bsl[nb * 32 + x0]);
                bf[ni][1] = __float_as_uint(Bsl[nb * 32 + x1]);
            }
#pragma unroll
            for (int mi = 0; mi < WM_AT; mi++)
#pragma unroll
                for (int ni = 0; ni < WN_AT; ni++)
                    MMA_TF32(c[mi][ni], af[mi][0], af[mi][1], af[mi][2],
                             af[mi][3], bf[ni][0], bf[ni][1]);
        }
    };

    // prologue: stages 0 .. STAGES-2
#pragma unroll
    for (int s = 0; s < STAGES - 1; s++)
        ISSUE(s, s << 5, s < ktiles);

    for (int kt = 0; kt < ktiles; kt++) {
        cp_wait<STAGES - 2>();
        __syncthreads();
        COMP(kt % STAGES);
        ISSUE((kt + STAGES - 1) % STAGES, (kt + STAGES - 1) << 5,
              kt + STAGES - 1 < ktiles);
    }

    // epilogue
#pragma unroll
    for (int mi = 0; mi < WM_AT; mi++) {
        int r0 = m0 + (wm * WM_AT + mi) * 16 + g;
#pragma unroll
        for (int ni = 0; ni < WN_AT; ni++) {
            int cc = n0 + (wn * WN_AT + ni) * 8 + 2 * tig;
            float b0v = bias[cc], b1v = bias[cc + 1];
            if (bias2) { b0v += bias2[cc]; b1v += bias2[cc + 1]; }
            float v0 = c[mi][ni][0] + b0v;
            float v1 = c[mi][ni][1] + b1v;
            float v2 = c[mi][ni][2] + b0v;
            float v3 = c[mi][ni][3] + b1v;
            if (act) {
                v0 = roundtf(tanhf(v0)); v1 = roundtf(tanhf(v1));
                v2 = roundtf(tanhf(v2)); v3 = roundtf(tanhf(v3));
            }
            *(float2*)(C + (size_t)r0 * N + cc)       = make_float2(v0, v1);
            *(float2*)(C + (size_t)(r0 + 8) * N + cc) = make_float2(v2, v3);
        }
    }
}

// ---------------------------------------------------------------------------
// Recurrence v5. 128 blocks x 512 threads; block owns 2 batch rows.
// Thread (i = tid&255, jh = tid>>8) handles unit i, j-half jh, both batches.
// W[i][jh*128 .. +64) in 32 ull REGISTERS (50% of W in RF);
// W[i][jh*128+64 .. +128) in smem (128KB, stride-17 float4 -> conflict-free).
// h pair-interleaved {b0,b1} per pair; ping-pong. 2-way j reduction via smem.
// Hall stores are tf32-rounded (the downstream GEMM consumes raw bits).
// ---------------------------------------------------------------------------
#define R5_WSTRIDE 17
#define R5_SMEM_BYTES (512*R5_WSTRIDE*16 + 2*128*16 + 512*8)  // 147456 B

__global__ __launch_bounds__(512, 1) void recurrence5_kernel(
    const float* __restrict__ Z, const float* __restrict__ Whh,
    float* __restrict__ Hall)
{
    extern __shared__ unsigned char rsm[];
    float4*     Wsm4 = (float4*)rsm;                               // [512][17]
    ulonglong2* hs2  = (ulonglong2*)(rsm + 512 * R5_WSTRIDE * 16); // [2][128]
    float2*     red  = (float2*)(rsm + 512 * R5_WSTRIDE * 16 + 4096); // [512]

    const int tid = threadIdx.x;
    const int i   = tid & 255;
    const int jh  = tid >> 8;
    const int b0  = blockIdx.x * 2;

    // W smem part: row r=(jh*256+i) holds cols [jh*128+64, jh*128+128) of unit i
    for (int idx = tid; idx < 512 * 16; idx += 512) {
        int r = idx >> 4, cc = idx & 15;
        int ui = r & 255, uh = r >> 8;
        Wsm4[r * R5_WSTRIDE + cc] =
            *(const float4*)(Whh + (size_t)ui * 256 + uh * 128 + 64 + cc * 4);
    }
    // W reg part: cols [jh*128, jh*128+64) as 32 packed pairs
    unsigned long long wr[32];
#pragma unroll
    for (int q = 0; q < 32; q++)
        wr[q] = *(const unsigned long long*)(Whh + (size_t)i * 256 + jh * 128 + 2 * q);

    if (tid < 256) {
        ulonglong2 zz; zz.x = 0ULL; zz.y = 0ULL;
        hs2[tid] = zz;   // covers both ping-pong buffers (2*128 entries)
    }
    const float a_i = (i < 86) ? 0.001f : (i < 171) ? 0.01f : 0.1f;
    float h0t = 0.0f, h1t = 0.0f;
    float z0 = 0.0f, z1 = 0.0f;
    if (tid < 256) {
        z0 = Z[(size_t)b0 * HDIM + tid];
        z1 = Z[(size_t)b0 * HDIM + 256 + tid];
    }
    __syncthreads();

    int cur = 0;
    for (int t = 0; t < TT; t++) {
        float zn0 = 0.0f, zn1 = 0.0f;
        if (tid < 256) {
            if (t + 1 < TT) {
                const float* Zn = Z + ((size_t)(t + 1) * BB + b0) * HDIM;
                zn0 = Zn[tid];
                zn1 = Zn[256 + tid];
            }
            // record pre-update h (tf32-rounded for the downstream GEMM)
            float* Ht = Hall + ((size_t)t * BB + b0) * HDIM;
            Ht[tid] = roundtf(h0t);
            Ht[256 + tid] = roundtf(h1t);
        }

        const ulonglong2* hc = hs2 + cur * 128;
        unsigned long long A0 = 0, B0 = 0, A1 = 0, B1 = 0;

        // register-resident W: pairs q -> cols jh*128 + 2q
#pragma unroll
        for (int q = 0; q < 32; q += 2) {
            ulonglong2 hva = hc[jh * 64 + q];
            ulonglong2 hvb = hc[jh * 64 + q + 1];
            FMA2(A0, wr[q], hva.x);     FMA2(A1, wr[q], hva.y);
            FMA2(B0, wr[q + 1], hvb.x); FMA2(B1, wr[q + 1], hvb.y);
        }
        // smem-resident W: chunk cc -> cols jh*128+64+4*cc (2 pairs)
        const ulonglong2* Wrow =
            (const ulonglong2*)(Wsm4 + (size_t)tid * R5_WSTRIDE);
#pragma unroll
        for (int cc = 0; cc < 16; cc++) {
            ulonglong2 wv  = Wrow[cc];
            ulonglong2 hva = hc[jh * 64 + 32 + 2 * cc];
            ulonglong2 hvb = hc[jh * 64 + 33 + 2 * cc];
            FMA2(A0, wv.x, hva.x); FMA2(A1, wv.x, hva.y);
            FMA2(B0, wv.y, hvb.x); FMA2(B1, wv.y, hvb.y);
        }

        ADD2(A0, B0);
        ADD2(A1, B1);
        float p0lo, p0hi, p1lo, p1hi;
        UNPACK2(p0lo, p0hi, A0);
        UNPACK2(p1lo, p1hi, A1);
        red[tid] = make_float2(p0lo + p0hi, p1lo + p1hi);
        __syncthreads();

        if (tid < 256) {
            float2 ra = red[tid], rb = red[256 + tid];
            float hr0 = tanhf(ra.x + rb.x + z0);
            float hr1 = tanhf(ra.y + rb.y + z1);
            h0t = fmaf(a_i, hr0 - h0t, h0t);
            h1t = fmaf(a_i, hr1 - h1t, h1t);
            float* hw = (float*)(hs2 + (cur ^ 1) * 128);
            hw[(tid >> 1) * 4 + (tid & 1)]     = h0t;
            hw[(tid >> 1) * 4 + (tid & 1) + 2] = h1t;
        }
        __syncthreads();
        cur ^= 1;
        z0 = zn0; z1 = zn1;
    }
}

// ---------------------------------------------------------------------------
// Launch. Input order: x,Wx0,bx0,Wx1,bx1,Wih,Whh,bih,bhh,Wh0,bh0,Wh1,bh1,Wg,bg
// ---------------------------------------------------------------------------
extern "C" void kernel_launch(void* const* d_in, const int* in_sizes, int n_in,
                              void* d_out, int out_size)
{
    const float* x   = (const float*)d_in[0];
    const float* Wx0 = (const float*)d_in[1];
    const float* bx0 = (const float*)d_in[2];
    const float* Wx1 = (const float*)d_in[3];
    const float* bx1 = (const float*)d_in[4];
    const float* Wih = (const float*)d_in[5];
    const float* Whh = (const float*)d_in[6];
    const float* bih = (const float*)d_in[7];
    const float* bhh = (const float*)d_in[8];
    const float* Wh0 = (const float*)d_in[9];
    const float* bh0 = (const float*)d_in[10];
    const float* Wh1 = (const float*)d_in[11];
    const float* bh1 = (const float*)d_in[12];
    const float* Wg  = (const float*)d_in[13];
    const float* bg  = (const float*)d_in[14];
    float* y = (float*)d_out;

    float *bufA, *bufB, *wr;
    cudaGetSymbolAddress((void**)&bufA, g_bufA);
    cudaGetSymbolAddress((void**)&bufB, g_bufB);
    cudaGetSymbolAddress((void**)&wr,  g_wr);

    auto GBig = gemm_cp_kernel<512, 4, 4, 128, 3>;  // BN=128, 16 warps
    auto GOut = gemm_cp_kernel<256, 4, 2, 64, 3>;   // BN=64,  8 warps

    const int smemBig = 3 * (4096 + 4096) * 4;   // 96 KB
    const int smemOut = 3 * (4096 + 2048) * 4;   // 72 KB
    cudaFuncSetAttribute(GBig, cudaFuncAttributeMaxDynamicSharedMemorySize, smemBig);
    cudaFuncSetAttribute(GOut, cudaFuncAttributeMaxDynamicSharedMemorySize, smemOut);
    cudaFuncSetAttribute(recurrence5_kernel,
                         cudaFuncAttributeMaxDynamicSharedMemorySize, R5_SMEM_BYTES);

    // --- pre-round inputs to tf32 ---
    // x -> bufB (consumed by GEMM1 before GEMM2 overwrites bufB)
    round_tf32_kernel<<<(MM * XDIM) / 4 / 256, 256>>>(x, bufB, MM * XDIM);
    round_tf32_kernel<<<16, 256>>>(Wx0, wr + WR_WX0, FDIM * XDIM);
    round_tf32_kernel<<<64, 256>>>(Wx1, wr + WR_WX1, FDIM * FDIM);
    round_tf32_kernel<<<64, 256>>>(Wih, wr + WR_WIH, HDIM * FDIM);
    round_tf32_kernel<<<64, 256>>>(Wh0, wr + WR_WH0, FDIM * HDIM);
    round_tf32_kernel<<<64, 256>>>(Wh1, wr + WR_WH1, FDIM * FDIM);
    round_tf32_kernel<<<16, 256>>>(Wg,  wr + WR_WG,  XDIM * FDIM);

    dim3 gBig(FDIM / 128, MM / 128);   // (2, 2048)
    dim3 gOut(1,          MM / 128);

    // feat1 = tanh(x @ Wx0^T + bx0)            -> bufA (rounded)
    GBig<<<gBig, 512, smemBig>>>(bufB, wr + WR_WX0, bx0, nullptr, bufA,
                                 MM, FDIM, XDIM, 1);
    // feat2 = tanh(feat1 @ Wx1^T + bx1)        -> bufB (rounded)
    GBig<<<gBig, 512, smemBig>>>(bufA, wr + WR_WX1, bx1, nullptr, bufB,
                                 MM, FDIM, FDIM, 1);
    // Z = feat2 @ Wih^T + bih + bhh            -> bufA (fp32)
    GBig<<<gBig, 512, smemBig>>>(bufB, wr + WR_WIH, bih, bhh, bufA,
                                 MM, HDIM, FDIM, 0);
    // scan: Hall[t] = round(h_t); h update     (Z in bufA, Hall -> bufB)
    recurrence5_kernel<<<BB / 2, 512, R5_SMEM_BYTES>>>(bufA, Whh, bufB);
    // d1 = tanh(Hall @ Wh0^T + bh0)            -> bufA (rounded)
    GBig<<<gBig, 512, smemBig>>>(bufB, wr + WR_WH0, bh0, nullptr, bufA,
                                 MM, FDIM, HDIM, 1);
    // d2 = tanh(d1 @ Wh1^T + bh1)              -> bufB (rounded)
    GBig<<<gBig, 512, smemBig>>>(bufA, wr + WR_WH1, bh1, nullptr, bufB,
                                 MM, FDIM, FDIM, 1);
    // y = d2 @ Wg^T + bg                       -> out (fp32)
    GOut<<<gOut, 256, smemOut>>>(bufB, wr + WR_WG, bg, nullptr, y,
                                 MM, XDIM, FDIM, 0);
}